// round 1
// baseline (speedup 1.0000x reference)
#include <cuda_runtime.h>
#include <math.h>

// Problem constants
#define T_LEN    2048
#define N_BATCH  16
#define C_CH     64
#define NSCALES  5
#define LMAX     5377            // 16*336 + 1
#define PAD      2689            // (LMAX+1)/2
#define XS_LEN   (T_LEN + 2*PAD) // 7426
#define MAX_TAPS 1280

__constant__ int c_widths[NSCALES] = {1, 27, 76, 167, 336};

__device__ double g_int_psi[1024];
__device__ int2   g_taps[NSCALES][MAX_TAPS];  // .x = offset (t-relative), .y = float bits of weight
__device__ int    g_cnt[NSCALES];

// ---------------------------------------------------------------------------
// Stage 1: integrated Morlet wavelet, replicating pywt/numpy bit-for-bit-ish.
//   t = linspace(-8, 8, 1024): t[i] = fl(i*delta) + (-8), t[1023] = 8.0
//   step = t[1] - t[0]  (NOT exactly 16/1023 — matters for the floor() below)
//   int_psi = cumsum(psi) * step  (serial cumsum in fp64 like numpy)
// __d*_rn intrinsics prevent any fast-math folding of the step expression.
// ---------------------------------------------------------------------------
__global__ void k_psi() {
    __shared__ double ps[1024];
    int i = threadIdx.x;
    double delta = 16.0 / 1023.0;
    double t = (i == 1023) ? 8.0 : __dadd_rn(__dmul_rn((double)i, delta), -8.0);
    ps[i] = __dmul_rn(exp(__dmul_rn(-0.5, __dmul_rn(t, t))), cos(__dmul_rn(5.0, t)));
    __syncthreads();
    if (i == 0) {
        double t1   = __dadd_rn(__dmul_rn(1.0, delta), -8.0);
        double step = __dsub_rn(t1, -8.0);
        double a = 0.0;
        for (int k = 0; k < 1024; ++k) {
            a = __dadd_rn(a, ps[k]);
            g_int_psi[k] = __dmul_rn(a, step);
        }
    }
}

// ---------------------------------------------------------------------------
// Stage 2: per-scale sparse tap tables.
//   f[l] = float(int_psi[trunc(l / (scale*step))]),  l in [0, Lf)
//   h[l] = f[l-1] - f[l], l in [0, Lf]  (f[-1] = f[Lf] = 0)
//   out[t] = sum_l h[l] * x[t + l - center],  center = Lf-1-(Lf-2)/2
//   Only nonzero h are stored (h == 0 exactly when j doesn't jump).
//   -sqrt(scale) folded into the weights.
// Deterministic compaction: chunked per-thread + serial prefix sum.
// ---------------------------------------------------------------------------
__global__ void k_taps() {
    __shared__ int s_cnt[1024];
    __shared__ int s_off[1024];
    __shared__ int s_Lf;
    int s   = blockIdx.x;
    int tid = threadIdx.x;
    int scale = c_widths[s];

    double delta = 16.0 / 1023.0;
    double step  = __dsub_rn(__dadd_rn(__dmul_rn(1.0, delta), -8.0), -8.0);
    double sstep = __dmul_rn((double)scale, step);
    int Lmax = scale * 16;

    if (tid == 0) {
        long long jm = (long long)(__ddiv_rn((double)Lmax, sstep));
        int Lf;
        if (jm < 1024) {
            Lf = Lmax + 1;
        } else {
            int lo = 0, hi = Lmax;
            while (lo < hi) {
                int mid = (lo + hi) >> 1;
                long long j = (long long)(__ddiv_rn((double)mid, sstep));
                if (j >= 1024) hi = mid; else lo = mid + 1;
            }
            Lf = lo;
        }
        s_Lf = Lf;
    }
    __syncthreads();
    int Lf = s_Lf;
    int total  = Lf + 1;                 // h indices 0..Lf
    int chunk  = (total + 1023) >> 10;   // <= 6
    int l0 = tid * chunk;
    int l1 = min(l0 + chunk, total);

    int lo_cut = (Lf - 2) / 2;
    int center = Lf - 1 - lo_cut;
    float negs = (float)(-sqrt((double)scale));

    float lw[8];
    int   loff[8];
    int   lc = 0;
    for (int l = l0; l < l1; ++l) {
        float fm1 = 0.0f, fcur = 0.0f;
        if (l >= 1) {
            long long j = (long long)(__ddiv_rn((double)(l - 1), sstep));
            fm1 = (float)g_int_psi[j];
        }
        if (l < Lf) {
            long long j = (long long)(__ddiv_rn((double)l, sstep));
            fcur = (float)g_int_psi[j];
        }
        float h = fm1 - fcur;
        if (h != 0.0f) {
            lw[lc]   = h * negs;
            loff[lc] = l - center;
            ++lc;
        }
    }
    s_cnt[tid] = lc;
    __syncthreads();
    if (tid == 0) {
        int a = 0;
        for (int i = 0; i < 1024; ++i) { s_off[i] = a; a += s_cnt[i]; }
        g_cnt[s] = (a > MAX_TAPS) ? MAX_TAPS : a;
    }
    __syncthreads();
    int base = s_off[tid];
    for (int i = 0; i < lc; ++i) {
        int pos = base + i;
        if (pos < MAX_TAPS)
            g_taps[s][pos] = make_int2(loff[i], __float_as_int(lw[i]));
    }
}

// ---------------------------------------------------------------------------
// Stage 3: main sparse correlation.
// One block per (n, c) row. Zero-padded row in SMEM (no bounds checks in the
// hot loop). Each thread accumulates 8 outputs at t = tid + r*256
// (lane-consecutive -> conflict-free LDS). Tap (off, w) is uniform per warp
// -> one broadcast LDS.64 per tap.
// ---------------------------------------------------------------------------
__global__ void __launch_bounds__(256) k_cwt(const float* __restrict__ x,
                                             float* __restrict__ out) {
    __shared__ float xs[XS_LEN];
    __shared__ int2  taps[MAX_TAPS];

    int b = blockIdx.x;
    int n = b >> 6;
    int c = b & 63;
    int tid = threadIdx.x;

    const float* xrow = x + ((size_t)n * T_LEN) * C_CH + c;
    for (int i = tid; i < XS_LEN; i += 256) {
        int u = i - PAD;
        xs[i] = (u >= 0 && u < T_LEN) ? xrow[(size_t)u * C_CH] : 0.0f;
    }

    for (int s = 0; s < NSCALES; ++s) {
        __syncthreads();   // also guards xs fill at s==0 / taps reuse afterward
        int cnt = g_cnt[s];
        for (int i = tid; i < cnt; i += 256) taps[i] = g_taps[s][i];
        __syncthreads();

        float a0 = 0.f, a1 = 0.f, a2 = 0.f, a3 = 0.f;
        float a4 = 0.f, a5 = 0.f, a6 = 0.f, a7 = 0.f;
        const float* base = xs + PAD + tid;

        #pragma unroll 2
        for (int k = 0; k < cnt; ++k) {
            int2 tp = taps[k];
            float w = __int_as_float(tp.y);
            const float* p = base + tp.x;
            a0 = fmaf(w, p[0],    a0);
            a1 = fmaf(w, p[256],  a1);
            a2 = fmaf(w, p[512],  a2);
            a3 = fmaf(w, p[768],  a3);
            a4 = fmaf(w, p[1024], a4);
            a5 = fmaf(w, p[1280], a5);
            a6 = fmaf(w, p[1536], a6);
            a7 = fmaf(w, p[1792], a7);
        }

        size_t ob = ((((size_t)n * T_LEN + tid) * C_CH) + c) * NSCALES + s;
        const size_t st = (size_t)256 * C_CH * NSCALES;  // 81920
        out[ob]        = a0;
        out[ob + st]   = a1;
        out[ob + 2*st] = a2;
        out[ob + 3*st] = a3;
        out[ob + 4*st] = a4;
        out[ob + 5*st] = a5;
        out[ob + 6*st] = a6;
        out[ob + 7*st] = a7;
    }
}

extern "C" void kernel_launch(void* const* d_in, const int* in_sizes, int n_in,
                              void* d_out, int out_size) {
    const float* x = (const float*)d_in[0];
    float* out = (float*)d_out;
    (void)in_sizes; (void)n_in; (void)out_size;

    k_psi<<<1, 1024>>>();
    k_taps<<<NSCALES, 1024>>>();
    k_cwt<<<N_BATCH * C_CH, 256>>>(x, out);
}